// round 14
// baseline (speedup 1.0000x reference)
#include <cuda_runtime.h>
#include <cuda_bf16.h>

#define NN 320
#define DD 256
#define GB 320   // scanloss grid; __launch_bounds__(320,3) -> >=444 resident
                 // CTAs >= 320 -> spin barrier is deadlock-free

// Scratch (allocation-free device globals)
__device__ float  g_L[NN * NN];       // logits (bit-exact symmetric)
__device__ float  g_E[NN * NN];       // exp(logits)
__device__ float  g_ys[NN];           // sorted y_times
__device__ int    g_perm[NN];         // sorted pos -> original index
__device__ int    g_se[NN];           // event class in sorted order
__device__ int    g_gt[NN];           // per k: count of !(ys-yk > 0)
__device__ int    g_geq[NN];          // per k: count of (ys-yk < 0)
__device__ float2 g_P[NN * (NN + 1)]; // per-row class-split E prefix sums
__device__ int    g_cnt[NN + 1];      // class-count prefix, packed c1<<10 | c0
__device__ float  g_loss[NN];
__device__ float  g_pos[NN];
__device__ int    g_bar;              // grid barrier (monotone across replays)
__device__ int    g_ctr;              // lossk completion (monotone across replays)

// TABLE rows packed: weight code c in {0,1,2} (weight = c*0.5) at bits [2v+1:2v],
// v = td + 3*e, td in {1(lower),2(middle),3(upper)}.
__constant__ int c_rb[7] = {8852, 5460, 4692, 5460, 5716, 4436, 8852};

typedef unsigned long long ull;

// Packed fp32x2 helpers (sm_103a FFMA2 path — only reachable via PTX).
// acc += (x + ny)^2 elementwise; x + (-y) is IEEE-identical to x - y.
__device__ __forceinline__ void dsq_acc(ull& acc, ull x, ull ny) {
    ull d;
    asm("add.rn.f32x2 %0, %1, %2;" : "=l"(d) : "l"(x), "l"(ny));
    asm("fma.rn.f32x2 %0, %1, %1, %0;" : "+l"(acc) : "l"(d));
}
__device__ __forceinline__ float dsum(ull acc) {
    unsigned lo, hi;
    asm("mov.b64 {%0, %1}, %2;" : "=r"(lo), "=r"(hi) : "l"(acc));
    return __uint_as_float(lo) + __uint_as_float(hi);
}

// ---------------------------------------------------------------------------
// Kernel 1: distances (blocks 0..99, f32x2-packed 2x2 micro-tiles over 32x32
// output tiles, K staged in 2 chunks) + exact rank sort / bounds (blocks
// 100,101). vs the 23.0us build: pad 33->34 (rows 16B-aligned, 272B stride)
// so the adjacent float2 pairs load as ONE LDS.128 each — half the load
// instructions and half the dependent-latency events per dd. A-load: 2
// distinct 16B addrs (broadcast); B-load: 16 distinct contiguous 16B ->
// conflict-free. Arithmetic unchanged: d = x + (-y) IEEE-identical to x - y;
// diag accumulates exactly +0 (reference row-max subtraction is a no-op).
// ---------------------------------------------------------------------------
__global__ void dist_kernel(const float* __restrict__ F,
                            const float* __restrict__ yt,
                            const int* __restrict__ ye) {
    __shared__ __align__(16) float2 sA[64][34];   // [dpair][i], 272B row stride
    __shared__ __align__(16) float2 sB[64][34];   // negated B tile
    __shared__ float  s_y[NN];
    int tx = threadIdx.x, ty = threadIdx.y;       // 16 x 16
    int tid = ty * 16 + tx;
    int b = blockIdx.x;

    if (b >= 100) {
        // --- sort / bounds block: 160 anchors each, O(N) exact counts ---
        for (int e = tid; e < NN; e += 256) s_y[e] = yt[e];
        __syncthreads();
        if (tid < 160) {
            int e = (b - 100) * 160 + tid;
            float v = s_y[e];
            int rank = 0, gt = 0, geq = 0;
#pragma unroll 8
            for (int j = 0; j < NN; j++) {
                float w = s_y[j];
                float d = w - v;                       // same float expr as reference pld
                rank += (w < v) || (w == v && j < e);  // unique tie-broken rank
                gt  += !(d > 0.0f);
                geq += (d < 0.0f);
            }
            g_ys[rank] = v; g_perm[rank] = e; g_se[rank] = __ldg(&ye[e]);
            g_gt[e] = gt; g_geq[e] = geq;
        }
        return;
    }

    int bi = (b / 10) * 32, bj = (b % 10) * 32;
    int row = tid >> 3;            // 0..31
    int col0 = (tid & 7) << 4;     // 0,16,...,112 (floats within 128-chunk)

    ull a00 = 0ull, a01 = 0ull, a10 = 0ull, a11 = 0ull;

    for (int s = 0; s < 2; s++) {
        const float* pA = F + (bi + row) * DD + s * 128 + col0;
        const float* pB = F + (bj + row) * DD + s * 128 + col0;
#pragma unroll
        for (int q = 0; q < 4; q++) {
            float4 av = *(const float4*)(pA + 4 * q);
            float4 bv = *(const float4*)(pB + 4 * q);
            int dp = (col0 + 4 * q) >> 1;
            sA[dp][row]     = make_float2(av.x, av.y);
            sA[dp + 1][row] = make_float2(av.z, av.w);
            sB[dp][row]     = make_float2(-bv.x, -bv.y);
            sB[dp + 1][row] = make_float2(-bv.z, -bv.w);
        }
        __syncthreads();
#pragma unroll 16
        for (int dd = 0; dd < 64; dd++) {
            ulonglong2 xv = *(const ulonglong2*)&sA[dd][2 * ty];   // x0, x1
            ulonglong2 yv = *(const ulonglong2*)&sB[dd][2 * tx];   // y0, y1
            dsq_acc(a00, xv.x, yv.x);
            dsq_acc(a01, xv.x, yv.y);
            dsq_acc(a10, xv.y, yv.x);
            dsq_acc(a11, xv.y, yv.y);
        }
        __syncthreads();
    }

    int i0 = bi + 2 * ty, j0 = bj + 2 * tx;
    float L;
    L = -0.5f * sqrtf(dsum(a00)); g_L[i0 * NN + j0]           = L; g_E[i0 * NN + j0]           = __expf(L);
    L = -0.5f * sqrtf(dsum(a01)); g_L[i0 * NN + j0 + 1]       = L; g_E[i0 * NN + j0 + 1]       = __expf(L);
    L = -0.5f * sqrtf(dsum(a10)); g_L[(i0 + 1) * NN + j0]     = L; g_E[(i0 + 1) * NN + j0]     = __expf(L);
    L = -0.5f * sqrtf(dsum(a11)); g_L[(i0 + 1) * NN + j0 + 1] = L; g_E[(i0 + 1) * NN + j0 + 1] = __expf(L);
}

// Grid barrier: all GB blocks resident (launch_bounds(320,3) -> >=444
// resident >= 320). Monotone counter: epoch = old/GB, correct across graph
// replays with no reset.
__device__ __forceinline__ void grid_barrier(int* bar, int t) {
    __threadfence();
    __syncthreads();
    if (t == 0) {
        int old = atomicAdd(bar, 1);
        int target = (old / GB + 1) * GB;
        while (atomicAdd(bar, 0) < target) __nanosleep(64);
    }
    __syncthreads();
}

// ---------------------------------------------------------------------------
// Kernel 2: scan + lossk fused with one grid barrier.
// Phase A: block i = class-split E prefix sums of row i. E row staged
//          COALESCED into smem, permutation gather via LDS (vs scattered LDG).
// Phase B: block k = per-anchor loss. Both binary searches rewritten as
//          fixed-step branchless lower-bounds (identical predicates -> same
//          indices) and interleaved for latency overlap; Pend/Pgt/Pgq L2
//          loads hoisted above the searches.
// ---------------------------------------------------------------------------
__global__ void __launch_bounds__(320, 3)
scanloss_kernel(const float* __restrict__ yt,
                const int* __restrict__ ye,
                float* __restrict__ out) {
    __shared__ float s_E[NN];
    __shared__ float ws0[10], ws1[10], wo0[10], wo1[10];
    __shared__ int   wsi[10], woi[10];
    __shared__ float s_ys[NN];
    __shared__ int   s_cnt[NN + 1];
    __shared__ int   s_rb[7];
    __shared__ float rS[10], rC[10];
    __shared__ int   s_last;

    int b = blockIdx.x, t = threadIdx.x;
    int lane = t & 31, w = t >> 5;

    // ================= Phase A: scan, row i = b ===========================
    {
        int i = b;
        s_E[t] = __ldg(&g_E[i * NN + t]);    // coalesced row read
        int pj = g_perm[t];
        int cls = g_se[t];
        __syncthreads();
        float Ev = (pj == i) ? 0.f : s_E[pj];   // eye mask folded; smem gather
        float x0 = cls ? 0.f : Ev;
        float x1 = cls ? Ev : 0.f;
        int   xc = cls ? (1 << 10) : 1;

#pragma unroll
        for (int off = 1; off < 32; off <<= 1) {
            float a0 = __shfl_up_sync(0xffffffffu, x0, off);
            float a1 = __shfl_up_sync(0xffffffffu, x1, off);
            int   ac = __shfl_up_sync(0xffffffffu, xc, off);
            if (lane >= off) { x0 += a0; x1 += a1; xc += ac; }
        }
        if (lane == 31) { ws0[w] = x0; ws1[w] = x1; wsi[w] = xc; }
        __syncthreads();
        if (t == 0) {
            float r0 = 0.f, r1 = 0.f; int ri = 0;
#pragma unroll
            for (int q = 0; q < 10; q++) {
                wo0[q] = r0; wo1[q] = r1; woi[q] = ri;
                r0 += ws0[q]; r1 += ws1[q]; ri += wsi[q];
            }
        }
        __syncthreads();
        x0 += wo0[w]; x1 += wo1[w];
        float2* Prow = g_P + i * (NN + 1);
        Prow[t + 1] = make_float2(x0, x1);
        if (t == 0) Prow[0] = make_float2(0.f, 0.f);
        if (i == 0) {
            g_cnt[t + 1] = xc + woi[w];
            if (t == 0) g_cnt[0] = 0;
        }
    }

    grid_barrier(&g_bar, t);

    // ================= Phase B: per-anchor loss, k = b =====================
    s_ys[t] = g_ys[t];
    s_cnt[t] = __ldcg(&g_cnt[t]);
    if (t == 0) s_cnt[NN] = __ldcg(&g_cnt[NN]);
    if (t < 7) s_rb[t] = c_rb[t];
    __syncthreads();

    {
        int k = b;
        float yk = __ldg(&yt[k]);
        int   ek = __ldg(&ye[k]);
        int   gt = g_gt[k], geq = g_geq[k];

        int   i  = t;
        float yi = yt[i];
        int   ei = ye[i];
        float pi = yi - yk;
        float a = fabsf(pi), na = -a;

        // Hoist L2 loads whose indices are known before the searches;
        // __ldcg: g_P written this launch by other SMs.
        const float2* Prow = g_P + i * (NN + 1);
        float2 Pend = __ldcg(&Prow[NN]);
        float2 Pgt  = __ldcg(&Prow[gt]);
        float2 Pgq  = __ldcg(&Prow[geq]);
        float Lki   = __ldg(&g_L[k * NN + i]);   // L symmetric

        int base = ei + 10 * ek;
        int cid = (pi > 0.f) ? base : ((pi < 0.f) ? -base : 0);
        int cidx = (cid == -11) ? 0 : (cid == -10) ? 1 : (cid == -1) ? 2 :
                   (cid == 0)   ? 3 : (cid == 1)   ? 4 : (cid == 10) ? 5 : 6;
        int rb = s_rb[cidx];

        // Branchless fixed-step lower bounds, interleaved (independent LDS
        // chains overlap). Predicates monotone (FP subtract monotone in
        // sorted ys) and use the identical float expressions as the
        // reference, so indices match the while-loop searches exactly.
        // hi: first m with (ys[m]-yk > a); lo: first m with !(ys[m]-yk < -a).
        int hi = 0, lo = 0;
#pragma unroll
        for (int step = 256; step > 0; step >>= 1) {
            int ph = hi + step;
            int pl = lo + step;
            bool okh = (ph <= NN) && !(s_ys[ph - 1] - yk > a);
            bool okl = (pl <= NN) && (s_ys[pl - 1] - yk < na);
            if (okh) hi = ph;
            if (okl) lo = pl;
        }

        float2 Phi  = __ldcg(&Prow[hi]);
        float2 Plo  = __ldcg(&Prow[lo]);
        float SU0 = Pend.x - Phi.x, SU1 = Pend.y - Phi.y;
        float SL0 = Plo.x,          SL1 = Plo.y;
        float SM0 = (Phi.x - Plo.x) - (Pgt.x - Pgq.x);
        float SM1 = (Phi.y - Plo.y) - (Pgt.y - Pgq.y);

        float w10 = (float)((rb >> 2)  & 3), w20 = (float)((rb >> 4)  & 3), w30 = (float)((rb >> 6)  & 3);
        float w11 = (float)((rb >> 8)  & 3), w21 = (float)((rb >> 10) & 3), w31 = (float)((rb >> 12) & 3);
        float denom = 0.5f * (w10 * SL0 + w11 * SL1 + w20 * SM0 + w21 * SM1 + w30 * SU0 + w31 * SU1);

        // Exact integer validity: counts of positive-weight elements.
        int cU = s_cnt[NN] - s_cnt[hi];
        int cL = s_cnt[lo];
        int cM = (s_cnt[hi] - s_cnt[lo]) - (s_cnt[gt] - s_cnt[geq]);
        if (pi != 0.f) cM -= (ei ? (1 << 10) : 1);   // i sits in middle, weight 0 (eye)
        int nz = rb | (rb >> 1);
        int vsum = ((nz >> 2) & 1) * (cL & 1023) + ((nz >> 8)  & 1) * (cL >> 10)
                 + ((nz >> 4) & 1) * (cM & 1023) + ((nz >> 10) & 1) * (cM >> 10)
                 + ((nz >> 6) & 1) * (cU & 1023) + ((nz >> 12) & 1) * (cU >> 10);
        bool valid = (vsum > 0) && (i != k);

        float res = valid ? (Lki - __logf(denom)) : 0.f;
        float c   = valid ? 1.f : 0.f;

#pragma unroll
        for (int sh = 16; sh > 0; sh >>= 1) {
            res += __shfl_xor_sync(0xffffffffu, res, sh);
            c   += __shfl_xor_sync(0xffffffffu, c,   sh);
        }
        if (lane == 0) { rS[w] = res; rC[w] = c; }
        __syncthreads();
        if (t == 0) {
            float S = 0.f, C = 0.f;
#pragma unroll
            for (int q = 0; q < 10; q++) { S += rS[q]; C += rC[q]; }
            g_loss[k] = (C > 0.f) ? (-S / C) : 0.f;
            g_pos[k]  = (C > 0.f) ? 1.f : 0.f;
            __threadfence();
            int old = atomicAdd(&g_ctr, 1);
            s_last = ((old % NN) == NN - 1);   // monotone: no reset across replays
        }
        __syncthreads();
        if (s_last) {
            float sa = __ldcg(&g_loss[t]), sb = __ldcg(&g_pos[t]);
#pragma unroll
            for (int sh = 16; sh > 0; sh >>= 1) {
                sa += __shfl_xor_sync(0xffffffffu, sa, sh);
                sb += __shfl_xor_sync(0xffffffffu, sb, sh);
            }
            if (lane == 0) { rS[w] = sa; rC[w] = sb; }
            __syncthreads();
            if (t == 0) {
                float S = 0.f, P = 0.f;
#pragma unroll
                for (int q = 0; q < 10; q++) { S += rS[q]; P += rC[q]; }
                out[0] = S / P;
            }
        }
    }
}

extern "C" void kernel_launch(void* const* d_in, const int* in_sizes, int n_in,
                              void* d_out, int out_size) {
    const float* features = (const float*)d_in[0];   // [320, 256] f32
    const float* y_times  = (const float*)d_in[1];   // [320] f32
    const int*   y_events = (const int*)d_in[2];     // [320] i32
    float* out = (float*)d_out;

    dist_kernel<<<102, dim3(16, 16)>>>(features, y_times, y_events);
    scanloss_kernel<<<GB, 320>>>(y_times, y_events, out);
}

// round 15
// speedup vs baseline: 1.1082x; 1.1082x over previous
#include <cuda_runtime.h>
#include <cuda_bf16.h>

#define NN 320
#define DD 256

// Scratch (allocation-free device globals)
__device__ float  g_L[NN * NN];   // logits (bit-exact symmetric)
__device__ float  g_E[NN * NN];   // exp(logits)
__device__ float  g_ys[NN];       // sorted y_times
__device__ int    g_perm[NN];     // sorted pos -> original index
__device__ int    g_se[NN];       // event class in sorted order
__device__ int    g_gt[NN];       // per k: count of !(ys-yk > 0)
__device__ int    g_geq[NN];      // per k: count of (ys-yk < 0)
__device__ float  g_S[NN];        // per-anchor logp sums (atomic; zeroed by dist)
__device__ float  g_C[NN];        // per-anchor valid counts (atomic; zeroed by dist)
__device__ int    g_ctr;          // block-completion counter (monotone across replays)

// TABLE rows packed: weight code c in {0,1,2} (weight = c*0.5) at bits [2v+1:2v],
// v = td + 3*e, td in {1(lower),2(middle),3(upper)}.
__constant__ int c_rb[7] = {8852, 5460, 4692, 5460, 5716, 4436, 8852};

typedef unsigned long long ull;

// Packed fp32x2 helpers (sm_103a FFMA2 path — only reachable via PTX).
// acc += (x + ny)^2 elementwise; x + (-y) is IEEE-identical to x - y.
__device__ __forceinline__ void dsq_acc(ull& acc, ull x, ull ny) {
    ull d;
    asm("add.rn.f32x2 %0, %1, %2;" : "=l"(d) : "l"(x), "l"(ny));
    asm("fma.rn.f32x2 %0, %1, %1, %0;" : "+l"(acc) : "l"(d));
}
__device__ __forceinline__ float dsum(ull acc) {
    unsigned lo, hi;
    asm("mov.b64 {%0, %1}, %2;" : "=r"(lo), "=r"(hi) : "l"(acc));
    return __uint_as_float(lo) + __uint_as_float(hi);
}

// ---------------------------------------------------------------------------
// Kernel 1 (R4-verbatim tiles): distances (blocks 0..99) + exact rank sort /
// bounds (blocks 100,101; these also zero the per-anchor accumulators before
// the scanloss launch). Row-max subtraction in the reference is a no-op
// (diag logit == 0 == row max); d = x + (-y) is IEEE-identical to x - y;
// (i,j)/(j,i) square negated diffs -> bit-exact symmetric L.
// ---------------------------------------------------------------------------
__global__ void dist_kernel(const float* __restrict__ F,
                            const float* __restrict__ yt,
                            const int* __restrict__ ye) {
    __shared__ float2 sA[64][33];   // [dpair][i], pad 33 kills STS conflicts
    __shared__ float2 sB[64][33];   // negated B tile
    __shared__ float  s_y[NN];
    int tx = threadIdx.x, ty = threadIdx.y;       // 16 x 16
    int tid = ty * 16 + tx;
    int b = blockIdx.x;

    if (b >= 100) {
        // --- sort / bounds block: 160 anchors each + accumulator zeroing ---
        for (int e = tid; e < NN; e += 256) s_y[e] = yt[e];
        __syncthreads();
        if (tid < 160) {
            int e = (b - 100) * 160 + tid;
            float v = s_y[e];
            int rank = 0, gt = 0, geq = 0;
#pragma unroll 8
            for (int j = 0; j < NN; j++) {
                float w = s_y[j];
                float d = w - v;                       // same float expr as reference pld
                rank += (w < v) || (w == v && j < e);  // unique tie-broken rank
                gt  += !(d > 0.0f);
                geq += (d < 0.0f);
            }
            g_ys[rank] = v; g_perm[rank] = e; g_se[rank] = __ldg(&ye[e]);
            g_gt[e] = gt; g_geq[e] = geq;
            g_S[e] = 0.f;                              // zero accumulators for
            g_C[e] = 0.f;                              // this run's scanloss
        }
        return;
    }

    int bi = (b / 10) * 32, bj = (b % 10) * 32;
    int row = tid >> 3;            // 0..31
    int col0 = (tid & 7) << 4;     // 0,16,...,112 (floats within 128-chunk)

    ull a00 = 0ull, a01 = 0ull, a10 = 0ull, a11 = 0ull;

    for (int s = 0; s < 2; s++) {
        const float* pA = F + (bi + row) * DD + s * 128 + col0;
        const float* pB = F + (bj + row) * DD + s * 128 + col0;
#pragma unroll
        for (int q = 0; q < 4; q++) {
            float4 av = *(const float4*)(pA + 4 * q);
            float4 bv = *(const float4*)(pB + 4 * q);
            int dp = (col0 + 4 * q) >> 1;
            sA[dp][row]     = make_float2(av.x, av.y);
            sA[dp + 1][row] = make_float2(av.z, av.w);
            sB[dp][row]     = make_float2(-bv.x, -bv.y);
            sB[dp + 1][row] = make_float2(-bv.z, -bv.w);
        }
        __syncthreads();
#pragma unroll 16
        for (int dd = 0; dd < 64; dd++) {
            ull x0 = *(const ull*)&sA[dd][2 * ty];
            ull x1 = *(const ull*)&sA[dd][2 * ty + 1];
            ull y0 = *(const ull*)&sB[dd][2 * tx];
            ull y1 = *(const ull*)&sB[dd][2 * tx + 1];
            dsq_acc(a00, x0, y0);
            dsq_acc(a01, x0, y1);
            dsq_acc(a10, x1, y0);
            dsq_acc(a11, x1, y1);
        }
        __syncthreads();
    }

    int i0 = bi + 2 * ty, j0 = bj + 2 * tx;
    float L;
    L = -0.5f * sqrtf(dsum(a00)); g_L[i0 * NN + j0]           = L; g_E[i0 * NN + j0]           = __expf(L);
    L = -0.5f * sqrtf(dsum(a01)); g_L[i0 * NN + j0 + 1]       = L; g_E[i0 * NN + j0 + 1]       = __expf(L);
    L = -0.5f * sqrtf(dsum(a10)); g_L[(i0 + 1) * NN + j0]     = L; g_E[(i0 + 1) * NN + j0]     = __expf(L);
    L = -0.5f * sqrtf(dsum(a11)); g_L[(i0 + 1) * NN + j0 + 1] = L; g_E[(i0 + 1) * NN + j0 + 1] = __expf(L);
}

// ---------------------------------------------------------------------------
// Kernel 2: ROW-MAJOR loss. Block i scans row i's class-split E prefix sums
// into SMEM, then thread k immediately computes logp(i,k) from those smem
// prefixes (no g_P global round trip, no grid barrier, no phase B restage):
//   - searches run on smem s_ys with thread-local yk
//   - L[i][k] is a coalesced row read (L bit-exact symmetric)
//   - per-anchor sums accumulate via spread-address atomicAdd
// The 320th block to finish (monotone ctr; blocks exit freely -> no deadlock
// possible) computes all loss_k and the final scalar. Summation order over i
// is atomic-nondeterministic: drift ~1e-7 rel (counts are exact 1.0f adds).
// ---------------------------------------------------------------------------
__global__ void __launch_bounds__(320)
scanloss_kernel(const float* __restrict__ yt,
                const int* __restrict__ ye,
                float* __restrict__ out) {
    __shared__ float s_E[NN];
    __shared__ float s_L[NN];
    __shared__ float s_ys[NN];
    __shared__ float s_P0[NN + 1], s_P1[NN + 1];
    __shared__ int   s_cnt[NN + 1];
    __shared__ float ws0[10], ws1[10], wo0[10], wo1[10];
    __shared__ int   wsi[10], woi[10];
    __shared__ int   s_rb[7];
    __shared__ float rS[10], rC[10];
    __shared__ int   s_last;

    int i = blockIdx.x, t = threadIdx.x;
    int lane = t & 31, w = t >> 5;

    // ---- Stage (all coalesced) ----
    s_E[t]  = __ldg(&g_E[i * NN + t]);
    s_L[t]  = __ldg(&g_L[i * NN + t]);    // row i of L == column i (symmetric)
    s_ys[t] = g_ys[t];
    if (t < 7) s_rb[t] = c_rb[t];
    int pj  = g_perm[t];
    int cls = g_se[t];
    __syncthreads();

    // ---- Class-split prefix scan of row i over sorted-j (eye folded) ----
    float Ev = (pj == i) ? 0.f : s_E[pj];
    float x0 = cls ? 0.f : Ev;
    float x1 = cls ? Ev : 0.f;
    int   xc = cls ? (1 << 10) : 1;
#pragma unroll
    for (int off = 1; off < 32; off <<= 1) {
        float a0 = __shfl_up_sync(0xffffffffu, x0, off);
        float a1 = __shfl_up_sync(0xffffffffu, x1, off);
        int   ac = __shfl_up_sync(0xffffffffu, xc, off);
        if (lane >= off) { x0 += a0; x1 += a1; xc += ac; }
    }
    if (lane == 31) { ws0[w] = x0; ws1[w] = x1; wsi[w] = xc; }
    __syncthreads();
    if (t == 0) {
        float r0 = 0.f, r1 = 0.f; int ri = 0;
#pragma unroll
        for (int q = 0; q < 10; q++) {
            wo0[q] = r0; wo1[q] = r1; woi[q] = ri;
            r0 += ws0[q]; r1 += ws1[q]; ri += wsi[q];
        }
    }
    __syncthreads();
    s_P0[t + 1]  = x0 + wo0[w];
    s_P1[t + 1]  = x1 + wo1[w];
    s_cnt[t + 1] = xc + woi[w];
    if (t == 0) { s_P0[0] = 0.f; s_P1[0] = 0.f; s_cnt[0] = 0; }
    __syncthreads();

    // ---- Thread k: logp(i,k) straight from smem prefixes ----
    {
        int k = t;
        float yk = __ldg(&yt[k]);
        int   ek = __ldg(&ye[k]);
        int   gt = g_gt[k], geq = g_geq[k];
        float yi = __ldg(&yt[i]);
        int   ei = __ldg(&ye[i]);

        float pi = yi - yk;                  // reference pld for element i, anchor k
        float a = fabsf(pi), na = -a;

        int base = ei + 10 * ek;
        int cid = (pi > 0.f) ? base : ((pi < 0.f) ? -base : 0);
        int cidx = (cid == -11) ? 0 : (cid == -10) ? 1 : (cid == -1) ? 2 :
                   (cid == 0)   ? 3 : (cid == 1)   ? 4 : (cid == 10) ? 5 : 6;
        int rb = s_rb[cidx];

        // Branchless fixed-step lower bounds, interleaved. Monotone predicates
        // with the identical float expressions as the reference -> exact
        // indices. hi: first m with ys[m]-yk > a; lo: first m !(ys[m]-yk < -a).
        int hi = 0, lo = 0;
#pragma unroll
        for (int step = 256; step > 0; step >>= 1) {
            int ph = hi + step;
            int pl = lo + step;
            bool okh = (ph <= NN) && !(s_ys[ph - 1] - yk > a);
            bool okl = (pl <= NN) && (s_ys[pl - 1] - yk < na);
            if (okh) hi = ph;
            if (okl) lo = pl;
        }

        float SU0 = s_P0[NN] - s_P0[hi], SU1 = s_P1[NN] - s_P1[hi];
        float SL0 = s_P0[lo],            SL1 = s_P1[lo];
        float SM0 = (s_P0[hi] - s_P0[lo]) - (s_P0[gt] - s_P0[geq]);
        float SM1 = (s_P1[hi] - s_P1[lo]) - (s_P1[gt] - s_P1[geq]);

        float w10 = (float)((rb >> 2)  & 3), w20 = (float)((rb >> 4)  & 3), w30 = (float)((rb >> 6)  & 3);
        float w11 = (float)((rb >> 8)  & 3), w21 = (float)((rb >> 10) & 3), w31 = (float)((rb >> 12) & 3);
        float denom = 0.5f * (w10 * SL0 + w11 * SL1 + w20 * SM0 + w21 * SM1 + w30 * SU0 + w31 * SU1);

        // Exact integer validity: counts of positive-weight elements.
        int cU = s_cnt[NN] - s_cnt[hi];
        int cL = s_cnt[lo];
        int cM = (s_cnt[hi] - s_cnt[lo]) - (s_cnt[gt] - s_cnt[geq]);
        if (pi != 0.f) cM -= (ei ? (1 << 10) : 1);   // element i sits in middle (eye)
        int nz = rb | (rb >> 1);
        int vsum = ((nz >> 2) & 1) * (cL & 1023) + ((nz >> 8)  & 1) * (cL >> 10)
                 + ((nz >> 4) & 1) * (cM & 1023) + ((nz >> 10) & 1) * (cM >> 10)
                 + ((nz >> 6) & 1) * (cU & 1023) + ((nz >> 12) & 1) * (cU >> 10);
        bool valid = (vsum > 0) && (i != k);

        if (valid) {
            float res = s_L[t] - __logf(denom);   // L[i][k], coalesced smem
            atomicAdd(&g_S[k], res);
            atomicAdd(&g_C[k], 1.f);
        }
    }

    // ---- Completion: 320th finisher computes all loss_k + final scalar ----
    __threadfence();
    __syncthreads();
    if (t == 0) {
        int old = atomicAdd(&g_ctr, 1);
        s_last = ((old % NN) == NN - 1);   // monotone: no reset across replays
    }
    __syncthreads();
    if (s_last) {
        float S = __ldcg(&g_S[t]);
        float C = __ldcg(&g_C[t]);
        float lk = (C > 0.f) ? (-S / C) : 0.f;
        float hp = (C > 0.f) ? 1.f : 0.f;
#pragma unroll
        for (int sh = 16; sh > 0; sh >>= 1) {
            lk += __shfl_xor_sync(0xffffffffu, lk, sh);
            hp += __shfl_xor_sync(0xffffffffu, hp, sh);
        }
        if (lane == 0) { rS[w] = lk; rC[w] = hp; }
        __syncthreads();
        if (t == 0) {
            float S2 = 0.f, P2 = 0.f;
#pragma unroll
            for (int q = 0; q < 10; q++) { S2 += rS[q]; P2 += rC[q]; }
            out[0] = S2 / P2;
        }
    }
}

extern "C" void kernel_launch(void* const* d_in, const int* in_sizes, int n_in,
                              void* d_out, int out_size) {
    const float* features = (const float*)d_in[0];   // [320, 256] f32
    const float* y_times  = (const float*)d_in[1];   // [320] f32
    const int*   y_events = (const int*)d_in[2];     // [320] i32
    float* out = (float*)d_out;

    dist_kernel<<<102, dim3(16, 16)>>>(features, y_times, y_events);
    scanloss_kernel<<<NN, NN>>>(y_times, y_events, out);
}

// round 16
// speedup vs baseline: 1.2280x; 1.1081x over previous
#include <cuda_runtime.h>
#include <cuda_bf16.h>

#define NN 320
#define DD 256
#define NB 422   // 100 dist tiles + 2 sort + 320 consumers

// Scratch (allocation-free device globals)
__device__ float  g_L[NN * NN];   // logits (bit-exact symmetric)
__device__ float  g_E[NN * NN];   // exp(logits)
__device__ float  g_ys[NN];       // sorted y_times
__device__ int    g_perm[NN];     // sorted pos -> original index
__device__ int    g_se[NN];       // event class in sorted order
__device__ int    g_gt[NN];       // per k: count of !(ys-yk > 0)
__device__ int    g_geq[NN];      // per k: count of (ys-yk < 0)
__device__ float  g_S[NN];        // per-anchor logp sums (atomic; zeroed by sort blocks)
__device__ float  g_C[NN];        // per-anchor valid counts (atomic; zeroed by sort blocks)
__device__ int    g_rflag[10];    // per-tile-row completion (monotone, +10/replay)
__device__ int    g_sflag;        // sort completion (monotone, +2/replay)
__device__ int    g_cons;         // consumer tickets (monotone, +320/replay)
__device__ int    g_ctr;          // consumer completion (monotone, +320/replay)

// TABLE rows packed: weight code c in {0,1,2} (weight = c*0.5) at bits [2v+1:2v],
// v = td + 3*e, td in {1(lower),2(middle),3(upper)}.
__constant__ int c_rb[7] = {8852, 5460, 4692, 5460, 5716, 4436, 8852};

typedef unsigned long long ull;

// Packed fp32x2 helpers (sm_103a FFMA2 path — only reachable via PTX).
// acc += (x + ny)^2 elementwise; x + (-y) is IEEE-identical to x - y.
__device__ __forceinline__ void dsq_acc(ull& acc, ull x, ull ny) {
    ull d;
    asm("add.rn.f32x2 %0, %1, %2;" : "=l"(d) : "l"(x), "l"(ny));
    asm("fma.rn.f32x2 %0, %1, %1, %0;" : "+l"(acc) : "l"(d));
}
__device__ __forceinline__ float dsum(ull acc) {
    unsigned lo, hi;
    asm("mov.b64 {%0, %1}, %2;" : "=r"(lo), "=r"(hi) : "l"(acc));
    return __uint_as_float(lo) + __uint_as_float(hi);
}

// Shared-memory union: dist tiles (33.8KB) vs consumer tables (7.7KB) vs sort.
struct SmemDist { float2 sA[64][33]; float2 sB[64][33]; };
struct SmemScan {
    float E[NN]; float L[NN]; float ys[NN];
    float P0[NN + 1]; float P1[NN + 1]; int cnt[NN + 1];
};
union SmemU { SmemDist d; SmemScan s; float y[NN]; };

// ---------------------------------------------------------------------------
// ONE launch, 422 blocks, producer/consumer via per-tile-row flags:
//  blocks 0..99   : 32x32 distance tiles (R15-verbatim math: d-major float2
//                   smem, FFMA2 subtract form; diag accumulates exactly +0,
//                   matching the reference's no-op row-max). Publishes
//                   g_rflag[row] after a threadfence.
//  blocks 100,101 : exact rank sort + run bounds + zero g_S/g_C; publishes
//                   g_sflag.
//  blocks 102..421: consumer i = b-102. Spins for its tile-row + sort flags
//                   (epoch from monotone ticket -> replay-safe), then scans
//                   row i's class-split E prefix sums in smem and computes
//                   logp(i,k) per thread k; per-anchor accumulation via
//                   spread-address atomicAdd. 320th finisher emits scalar.
// Residency: smem 34KB -> 6 blocks/SM; threads 320 -> 6/SM; launch_bounds
// (320,3) caps regs. All 422 blocks wave-1 resident -> spins are safe (and
// producers have lower block ids regardless).
// ---------------------------------------------------------------------------
__global__ void __launch_bounds__(320, 3)
fused_all(const float* __restrict__ F,
          const float* __restrict__ yt,
          const int* __restrict__ ye,
          float* __restrict__ out) {
    __shared__ SmemU sm;
    __shared__ float ws0[10], ws1[10], wo0[10], wo1[10];
    __shared__ int   wsi[10], woi[10];
    __shared__ int   s_rb[7];
    __shared__ float rS[10], rC[10];
    __shared__ int   s_last;

    int b = blockIdx.x;
    int t = threadIdx.x;          // 0..319
    int lane = t & 31, w = t >> 5;

    if (b < 100) {
        // ==================== dist tile producer ====================
        bool act = (t < 256);
        int row = t >> 3;             // 0..31 (t<256)
        int col0 = (t & 7) << 4;      // 0,16,...,112 floats in 128-chunk
        int tx = t & 15, ty = (t >> 4) & 15;
        int bi = (b / 10) * 32, bj = (b % 10) * 32;
        ull a00 = 0ull, a01 = 0ull, a10 = 0ull, a11 = 0ull;

        for (int s = 0; s < 2; s++) {
            if (act) {
                const float* pA = F + (bi + row) * DD + s * 128 + col0;
                const float* pB = F + (bj + row) * DD + s * 128 + col0;
#pragma unroll
                for (int q = 0; q < 4; q++) {
                    float4 av = *(const float4*)(pA + 4 * q);
                    float4 bv = *(const float4*)(pB + 4 * q);
                    int dp = (col0 + 4 * q) >> 1;
                    sm.d.sA[dp][row]     = make_float2(av.x, av.y);
                    sm.d.sA[dp + 1][row] = make_float2(av.z, av.w);
                    sm.d.sB[dp][row]     = make_float2(-bv.x, -bv.y);
                    sm.d.sB[dp + 1][row] = make_float2(-bv.z, -bv.w);
                }
            }
            __syncthreads();
            if (act) {
#pragma unroll 16
                for (int dd = 0; dd < 64; dd++) {
                    ull x0 = *(const ull*)&sm.d.sA[dd][2 * ty];
                    ull x1 = *(const ull*)&sm.d.sA[dd][2 * ty + 1];
                    ull y0 = *(const ull*)&sm.d.sB[dd][2 * tx];
                    ull y1 = *(const ull*)&sm.d.sB[dd][2 * tx + 1];
                    dsq_acc(a00, x0, y0);
                    dsq_acc(a01, x0, y1);
                    dsq_acc(a10, x1, y0);
                    dsq_acc(a11, x1, y1);
                }
            }
            __syncthreads();
        }
        if (act) {
            int i0 = bi + 2 * ty, j0 = bj + 2 * tx;
            float L;
            L = -0.5f * sqrtf(dsum(a00)); g_L[i0 * NN + j0]           = L; g_E[i0 * NN + j0]           = __expf(L);
            L = -0.5f * sqrtf(dsum(a01)); g_L[i0 * NN + j0 + 1]       = L; g_E[i0 * NN + j0 + 1]       = __expf(L);
            L = -0.5f * sqrtf(dsum(a10)); g_L[(i0 + 1) * NN + j0]     = L; g_E[(i0 + 1) * NN + j0]     = __expf(L);
            L = -0.5f * sqrtf(dsum(a11)); g_L[(i0 + 1) * NN + j0 + 1] = L; g_E[(i0 + 1) * NN + j0 + 1] = __expf(L);
        }
        __threadfence();
        __syncthreads();
        if (t == 0) atomicAdd(&g_rflag[b / 10], 1);   // monotone: +10/row/replay
        return;
    }

    if (b < 102) {
        // ==================== sort / bounds producer ====================
        sm.y[t] = yt[t];
        __syncthreads();
        if (t < 160) {
            int e = (b - 100) * 160 + t;
            float v = sm.y[e];
            int rank = 0, gt = 0, geq = 0;
#pragma unroll 8
            for (int j = 0; j < NN; j++) {
                float wv = sm.y[j];
                float d = wv - v;                        // same float expr as reference pld
                rank += (wv < v) || (wv == v && j < e);  // unique tie-broken rank
                gt  += !(d > 0.0f);
                geq += (d < 0.0f);
            }
            g_ys[rank] = v; g_perm[rank] = e; g_se[rank] = __ldg(&ye[e]);
            g_gt[e] = gt; g_geq[e] = geq;
            g_S[e] = 0.f;                                // zero this replay's accumulators
            g_C[e] = 0.f;
        }
        __threadfence();
        __syncthreads();
        if (t == 0) atomicAdd(&g_sflag, 1);              // monotone: +2/replay
        return;
    }

    // ======================== consumer: row i ==========================
    int i = b - 102;

    // Wait for sort + this row's 10 tiles. Epoch from monotone ticket.
    if (t == 0) {
        int ticket = atomicAdd(&g_cons, 1);
        int epoch = ticket / NN;
        int ts = (epoch + 1) * 2;
        int tr = (epoch + 1) * 10;
        while (atomicAdd(&g_sflag, 0) < ts) __nanosleep(128);
        int* rf = &g_rflag[i >> 5];
        while (atomicAdd(rf, 0) < tr) __nanosleep(128);
    }
    __syncthreads();

    // ---- Stage (producer data: __ldcg — same-launch cross-SM) ----
    sm.s.E[t]  = __ldcg(&g_E[i * NN + t]);
    sm.s.L[t]  = __ldcg(&g_L[i * NN + t]);    // row i of L == column i (symmetric)
    sm.s.ys[t] = __ldcg(&g_ys[t]);
    if (t < 7) s_rb[t] = c_rb[t];
    int pj  = __ldcg(&g_perm[t]);
    int cls = __ldcg(&g_se[t]);
    __syncthreads();

    // ---- Class-split prefix scan of row i over sorted-j (eye folded) ----
    float Ev = (pj == i) ? 0.f : sm.s.E[pj];
    float x0 = cls ? 0.f : Ev;
    float x1 = cls ? Ev : 0.f;
    int   xc = cls ? (1 << 10) : 1;
#pragma unroll
    for (int off = 1; off < 32; off <<= 1) {
        float a0 = __shfl_up_sync(0xffffffffu, x0, off);
        float a1 = __shfl_up_sync(0xffffffffu, x1, off);
        int   ac = __shfl_up_sync(0xffffffffu, xc, off);
        if (lane >= off) { x0 += a0; x1 += a1; xc += ac; }
    }
    if (lane == 31) { ws0[w] = x0; ws1[w] = x1; wsi[w] = xc; }
    __syncthreads();
    if (t == 0) {
        float r0 = 0.f, r1 = 0.f; int ri = 0;
#pragma unroll
        for (int q = 0; q < 10; q++) {
            wo0[q] = r0; wo1[q] = r1; woi[q] = ri;
            r0 += ws0[q]; r1 += ws1[q]; ri += wsi[q];
        }
    }
    __syncthreads();
    sm.s.P0[t + 1]  = x0 + wo0[w];
    sm.s.P1[t + 1]  = x1 + wo1[w];
    sm.s.cnt[t + 1] = xc + woi[w];
    if (t == 0) { sm.s.P0[0] = 0.f; sm.s.P1[0] = 0.f; sm.s.cnt[0] = 0; }
    __syncthreads();

    // ---- Thread k: logp(i,k) straight from smem prefixes ----
    {
        int k = t;
        float yk = __ldg(&yt[k]);
        int   ek = __ldg(&ye[k]);
        int   gt = __ldcg(&g_gt[k]), geq = __ldcg(&g_geq[k]);
        float yi = __ldg(&yt[i]);
        int   ei = __ldg(&ye[i]);

        float pi = yi - yk;                  // reference pld for element i, anchor k
        float a = fabsf(pi), na = -a;

        int base = ei + 10 * ek;
        int cid = (pi > 0.f) ? base : ((pi < 0.f) ? -base : 0);
        int cidx = (cid == -11) ? 0 : (cid == -10) ? 1 : (cid == -1) ? 2 :
                   (cid == 0)   ? 3 : (cid == 1)   ? 4 : (cid == 10) ? 5 : 6;
        int rb = s_rb[cidx];

        // Branchless fixed-step lower bounds, interleaved. Monotone predicates
        // with the identical float expressions as the reference -> exact
        // indices. hi: first m with ys[m]-yk > a; lo: first m !(ys[m]-yk < -a).
        int hi = 0, lo = 0;
#pragma unroll
        for (int step = 256; step > 0; step >>= 1) {
            int ph = hi + step;
            int pl = lo + step;
            bool okh = (ph <= NN) && !(sm.s.ys[ph - 1] - yk > a);
            bool okl = (pl <= NN) && (sm.s.ys[pl - 1] - yk < na);
            if (okh) hi = ph;
            if (okl) lo = pl;
        }

        float SU0 = sm.s.P0[NN] - sm.s.P0[hi], SU1 = sm.s.P1[NN] - sm.s.P1[hi];
        float SL0 = sm.s.P0[lo],               SL1 = sm.s.P1[lo];
        float SM0 = (sm.s.P0[hi] - sm.s.P0[lo]) - (sm.s.P0[gt] - sm.s.P0[geq]);
        float SM1 = (sm.s.P1[hi] - sm.s.P1[lo]) - (sm.s.P1[gt] - sm.s.P1[geq]);

        float w10 = (float)((rb >> 2)  & 3), w20 = (float)((rb >> 4)  & 3), w30 = (float)((rb >> 6)  & 3);
        float w11 = (float)((rb >> 8)  & 3), w21 = (float)((rb >> 10) & 3), w31 = (float)((rb >> 12) & 3);
        float denom = 0.5f * (w10 * SL0 + w11 * SL1 + w20 * SM0 + w21 * SM1 + w30 * SU0 + w31 * SU1);

        // Exact integer validity: counts of positive-weight elements.
        int cU = sm.s.cnt[NN] - sm.s.cnt[hi];
        int cL = sm.s.cnt[lo];
        int cM = (sm.s.cnt[hi] - sm.s.cnt[lo]) - (sm.s.cnt[gt] - sm.s.cnt[geq]);
        if (pi != 0.f) cM -= (ei ? (1 << 10) : 1);   // element i sits in middle (eye)
        int nz = rb | (rb >> 1);
        int vsum = ((nz >> 2) & 1) * (cL & 1023) + ((nz >> 8)  & 1) * (cL >> 10)
                 + ((nz >> 4) & 1) * (cM & 1023) + ((nz >> 10) & 1) * (cM >> 10)
                 + ((nz >> 6) & 1) * (cU & 1023) + ((nz >> 12) & 1) * (cU >> 10);
        bool valid = (vsum > 0) && (i != k);

        if (valid) {
            float res = sm.s.L[t] - __logf(denom);   // L[i][k]
            atomicAdd(&g_S[k], res);
            atomicAdd(&g_C[k], 1.f);
        }
    }

    // ---- Completion: 320th consumer computes all loss_k + final scalar ----
    __threadfence();
    __syncthreads();
    if (t == 0) {
        int old = atomicAdd(&g_ctr, 1);
        s_last = ((old % NN) == NN - 1);   // monotone: no reset across replays
    }
    __syncthreads();
    if (s_last) {
        float S = __ldcg(&g_S[t]);
        float C = __ldcg(&g_C[t]);
        float lk = (C > 0.f) ? (-S / C) : 0.f;
        float hp = (C > 0.f) ? 1.f : 0.f;
#pragma unroll
        for (int sh = 16; sh > 0; sh >>= 1) {
            lk += __shfl_xor_sync(0xffffffffu, lk, sh);
            hp += __shfl_xor_sync(0xffffffffu, hp, sh);
        }
        if (lane == 0) { rS[w] = lk; rC[w] = hp; }
        __syncthreads();
        if (t == 0) {
            float S2 = 0.f, P2 = 0.f;
#pragma unroll
            for (int q = 0; q < 10; q++) { S2 += rS[q]; P2 += rC[q]; }
            out[0] = S2 / P2;
        }
    }
}

extern "C" void kernel_launch(void* const* d_in, const int* in_sizes, int n_in,
                              void* d_out, int out_size) {
    const float* features = (const float*)d_in[0];   // [320, 256] f32
    const float* y_times  = (const float*)d_in[1];   // [320] f32
    const int*   y_events = (const int*)d_in[2];     // [320] i32
    float* out = (float*)d_out;

    fused_all<<<NB, 320>>>(features, y_times, y_events, out);
}